// round 7
// baseline (speedup 1.0000x reference)
#include <cuda_runtime.h>
#include <math.h>

#define D_MODEL 1024
#define N_HEADS 16
#define D_HEAD  64
#define SEQ     2048
#define BATCH   2
#define MTOT    (BATCH*SEQ)      /* 4096 */
#define QKV_N   (3*D_MODEL)      /* 3072 */

typedef unsigned long long u64;

// Packed f32x2 helpers (Blackwell sm_10x: dual-fp32 per instruction)
__device__ __forceinline__ void ffma2(u64& d, u64 a, u64 b) {
    asm("fma.rn.f32x2 %0, %1, %2, %0;" : "+l"(d) : "l"(a), "l"(b));
}
__device__ __forceinline__ u64 pack2(float x, float y) {
    u64 r; asm("mov.b64 %0, {%1, %2};" : "=l"(r) : "f"(x), "f"(y)); return r;
}
__device__ __forceinline__ u64 dup2(float x) {
    u64 r; asm("mov.b64 %0, {%1, %1};" : "=l"(r) : "f"(x)); return r;
}
__device__ __forceinline__ void unpack2(float& lo, float& hi, u64 v) {
    asm("mov.b64 {%0, %1}, %2;" : "=f"(lo), "=f"(hi) : "l"(v));
}
__device__ __forceinline__ u64 mul2(u64 a, u64 b) {
    u64 r; asm("mul.rn.f32x2 %0, %1, %2;" : "=l"(r) : "l"(a), "l"(b)); return r;
}

// Scratch (device globals; no allocations allowed)
__device__ float g_qkv[(size_t)MTOT*QKV_N];    // [M][3072]: q|k|v per row
__device__ float g_qt[(size_t)BATCH*N_HEADS*D_HEAD*SEQ]; // [B][H][64][S] d-major, rope'd
__device__ float g_kt[(size_t)BATCH*N_HEADS*D_HEAD*SEQ]; // [B][H][64][S] d-major, rope'd
__device__ float g_ctx[(size_t)MTOT*D_MODEL];  // [M][1024]: attention output

// ---------------------------------------------------------------------------
// GEMM: C[m][n] = sum_k A[m][k]*B[n][k] + bias[n]   (both K-major)
// 128x128 tile, BK=16, 256 threads, 8x8 micro-tile as 8x4 f32x2 pairs (FFMA2).
// Smem stride 136 -> conflict-free transpose stores.
// ---------------------------------------------------------------------------
__global__ void __launch_bounds__(256, 2) sgemm_nt_bias(
    const float* __restrict__ A, const float* __restrict__ B,
    const float* __restrict__ bias, float* __restrict__ C,
    int M, int N, int K)
{
    __shared__ float As[16][136];
    __shared__ float Bs[16][136];

    const int bm = blockIdx.y * 128;
    const int bn = blockIdx.x * 128;
    const int tid = threadIdx.x;
    const int tx = tid & 15, ty = tid >> 4;

    u64 acc[8][4];
#pragma unroll
    for (int i = 0; i < 8; i++)
#pragma unroll
        for (int j = 0; j < 4; j++) acc[i][j] = 0ull;

    const float* Ab = A + (size_t)bm * K;
    const float* Bb = B + (size_t)bn * K;

    for (int k0 = 0; k0 < K; k0 += 16) {
#pragma unroll
        for (int l = 0; l < 2; l++) {
            int f   = tid + l * 256;       // float4 id: 512 total
            int row = f >> 2;              // 0..127
            int c4  = (f & 3) * 4;         // 0,4,8,12
            float4 av = *(const float4*)(Ab + (size_t)row * K + k0 + c4);
            As[c4+0][row] = av.x; As[c4+1][row] = av.y;
            As[c4+2][row] = av.z; As[c4+3][row] = av.w;
            float4 bv = *(const float4*)(Bb + (size_t)row * K + k0 + c4);
            Bs[c4+0][row] = bv.x; Bs[c4+1][row] = bv.y;
            Bs[c4+2][row] = bv.z; Bs[c4+3][row] = bv.w;
        }
        __syncthreads();
#pragma unroll
        for (int k = 0; k < 16; k++) {
            float a[8];
            *(float4*)(a)     = *(const float4*)&As[k][ty*8];
            *(float4*)(a + 4) = *(const float4*)&As[k][ty*8 + 4];
            float4 bl = *(const float4*)&Bs[k][tx*8];
            float4 bh = *(const float4*)&Bs[k][tx*8 + 4];
            u64 bp[4];
            bp[0] = pack2(bl.x, bl.y); bp[1] = pack2(bl.z, bl.w);
            bp[2] = pack2(bh.x, bh.y); bp[3] = pack2(bh.z, bh.w);
#pragma unroll
            for (int i = 0; i < 8; i++) {
                u64 ap = dup2(a[i]);
#pragma unroll
                for (int j = 0; j < 4; j++)
                    ffma2(acc[i][j], ap, bp[j]);
            }
        }
        __syncthreads();
    }

#pragma unroll
    for (int i = 0; i < 8; i++) {
        int row = bm + ty*8 + i;
#pragma unroll
        for (int j4 = 0; j4 < 2; j4++) {
            int col = bn + tx*8 + j4*4;
            float4 o;
            unpack2(o.x, o.y, acc[i][j4*2+0]);
            unpack2(o.z, o.w, acc[i][j4*2+1]);
            o.x += bias[col+0]; o.y += bias[col+1];
            o.z += bias[col+2]; o.w += bias[col+3];
            *(float4*)(C + (size_t)row * N + col) = o;
        }
    }
}

// ---------------------------------------------------------------------------
// RoPE + transpose: read q,k from g_qkv, rotate, write d-major [B][H][64][S].
// ---------------------------------------------------------------------------
__global__ void __launch_bounds__(256) rope_transpose(
    const float* __restrict__ qkv, float* __restrict__ qt, float* __restrict__ kt)
{
    __shared__ float Tq[64*65];
    __shared__ float Tk[64*65];

    const int st = blockIdx.x, h = blockIdx.y, b = blockIdx.z;
    const int s0 = st * 64;
    const int tid = threadIdx.x;

#pragma unroll
    for (int l = 0; l < 4; l++) {
        int f = tid + l * 256;
        int srow = f >> 4;
        int d4 = (f & 15) * 4;
        const float* p = qkv + (size_t)(b * SEQ + s0 + srow) * QKV_N + h * 64 + d4;
        float4 qv = *(const float4*)p;
        float4 kv = *(const float4*)(p + D_MODEL);
        Tq[srow*65 + d4+0] = qv.x; Tq[srow*65 + d4+1] = qv.y;
        Tq[srow*65 + d4+2] = qv.z; Tq[srow*65 + d4+3] = qv.w;
        Tk[srow*65 + d4+0] = kv.x; Tk[srow*65 + d4+1] = kv.y;
        Tk[srow*65 + d4+2] = kv.z; Tk[srow*65 + d4+3] = kv.w;
    }
    __syncthreads();

    const size_t obase = ((size_t)(b * N_HEADS + h)) * D_HEAD * SEQ;
#pragma unroll
    for (int l = 0; l < 4; l++) {
        int f = tid + l * 256;
        int d = f >> 4;
        int s4 = (f & 15) * 4;
        int i = d & 31;
        bool hi = d >= 32;
        float inv = powf(10000.0f, -(2.0f * (float)i) / 64.0f);
        float4 oq, ok;
        float* pq = (float*)&oq;
        float* pk = (float*)&ok;
#pragma unroll
        for (int u = 0; u < 4; u++) {
            int s = s4 + u;
            float ang = (float)(s0 + s) * inv;
            float sn, cs;
            sincosf(ang, &sn, &cs);
            float q1 = Tq[s*65 + d], q2 = Tq[s*65 + (d ^ 32)];
            float k1 = Tk[s*65 + d], k2 = Tk[s*65 + (d ^ 32)];
            pq[u] = hi ? (q1 * cs + q2 * sn) : (q1 * cs - q2 * sn);
            pk[u] = hi ? (k1 * cs + k2 * sn) : (k1 * cs - k2 * sn);
        }
        *(float4*)(qt + obase + (size_t)d * SEQ + s0 + s4) = oq;
        *(float4*)(kt + obase + (size_t)d * SEQ + s0 + s4) = ok;
    }
}

// ---------------------------------------------------------------------------
// Flash attention, causal, FFMA2 inner loops. Block per (q-tile 64, head, b).
// ---------------------------------------------------------------------------
__global__ void __launch_bounds__(256, 2) attn_kernel(
    const float* __restrict__ qt, const float* __restrict__ ktb,
    const float* __restrict__ qkv, float* __restrict__ ctx)
{
    __shared__ float Qs[64*64];   // [d][s-local]
    __shared__ float KP[64*64];   // K: [d][s-local]; then P: [q-row][j]
    __shared__ float Vs[64*64];   // [j][d]

    const int qtile = blockIdx.x, h = blockIdx.y, b = blockIdx.z;
    const int tid = threadIdx.x;
    const int tx = tid & 15, ty = tid >> 4;
    const int qBase = qtile * 64;

    const size_t hbase = ((size_t)(b * N_HEADS + h)) * D_HEAD * SEQ;
    const float* qtp = qt + hbase;
    const float* ktp = ktb + hbase;
    const float* vbase = qkv + (size_t)b * SEQ * QKV_N + 2 * D_MODEL + h * 64;

#pragma unroll
    for (int l = 0; l < 4; l++) {
        int f = tid + l * 256;
        int d = f >> 4;
        int s4 = (f & 15) * 4;
        *(float4*)&Qs[d*64 + s4] =
            *(const float4*)(qtp + (size_t)d * SEQ + qBase + s4);
    }

    // Prologue: K/V tile 0 into registers
    float4 kreg[4], vreg[4];
#pragma unroll
    for (int l = 0; l < 4; l++) {
        int f = tid + l * 256;
        int d = f >> 4;
        int c4 = (f & 15) * 4;
        kreg[l] = *(const float4*)(ktp + (size_t)d * SEQ + 0 + c4);
        vreg[l] = *(const float4*)(vbase + (size_t)(0 + d) * QKV_N + c4);
    }

    float m_i[4], l_i[4];
    u64 acc[4][2];
#pragma unroll
    for (int r = 0; r < 4; r++) {
        m_i[r] = -1e30f; l_i[r] = 0.f;
        acc[r][0] = 0ull; acc[r][1] = 0ull;
    }

    for (int kt = 0; kt <= qtile; kt++) {
        __syncthreads();   // (A)

#pragma unroll
        for (int l = 0; l < 4; l++) {
            int f = tid + l * 256;
            int d = f >> 4;
            int c4 = (f & 15) * 4;
            *(float4*)&KP[d*64 + c4] = kreg[l];
            *(float4*)&Vs[d*64 + c4] = vreg[l];
        }
        __syncthreads();   // (B)

        if (kt < qtile) {   // prefetch next tile under compute
            const int nBase = (kt + 1) * 64;
#pragma unroll
            for (int l = 0; l < 4; l++) {
                int f = tid + l * 256;
                int d = f >> 4;
                int c4 = (f & 15) * 4;
                kreg[l] = *(const float4*)(ktp + (size_t)d * SEQ + nBase + c4);
                vreg[l] = *(const float4*)(vbase + (size_t)(nBase + d) * QKV_N + c4);
            }
        }

        // S = Q K^T, packed pairs over columns
        u64 s2[4][2];
#pragma unroll
        for (int r = 0; r < 4; r++) { s2[r][0] = 0ull; s2[r][1] = 0ull; }
#pragma unroll 16
        for (int d = 0; d < 64; d++) {
            float4 a  = *(const float4*)&Qs[d*64 + ty*4];
            float4 bb = *(const float4*)&KP[d*64 + tx*4];
            u64 bp0 = pack2(bb.x, bb.y);
            u64 bp1 = pack2(bb.z, bb.w);
            float av[4] = {a.x, a.y, a.z, a.w};
#pragma unroll
            for (int r = 0; r < 4; r++) {
                u64 ap = dup2(av[r]);
                ffma2(s2[r][0], ap, bp0);
                ffma2(s2[r][1], ap, bp1);
            }
        }

        float s[4][4];
#pragma unroll
        for (int r = 0; r < 4; r++) {
            unpack2(s[r][0], s[r][1], s2[r][0]);
            unpack2(s[r][2], s[r][3], s2[r][1]);
#pragma unroll
            for (int c = 0; c < 4; c++) s[r][c] *= 0.125f;
        }

        if (kt == qtile) {   // diagonal tile: causal mask
#pragma unroll
            for (int r = 0; r < 4; r++)
#pragma unroll
                for (int c = 0; c < 4; c++)
                    if (tx*4 + c > ty*4 + r) s[r][c] = -1e30f;
        }

        // Online softmax (row stats across 16 tx lanes)
#pragma unroll
        for (int r = 0; r < 4; r++) {
            float mt = fmaxf(fmaxf(s[r][0], s[r][1]), fmaxf(s[r][2], s[r][3]));
#pragma unroll
            for (int off = 1; off < 16; off <<= 1)
                mt = fmaxf(mt, __shfl_xor_sync(0xffffffffu, mt, off));
            float mnew  = fmaxf(m_i[r], mt);
            float alpha = __expf(m_i[r] - mnew);
            float sum = 0.f;
#pragma unroll
            for (int c = 0; c < 4; c++) {
                s[r][c] = __expf(s[r][c] - mnew);
                sum += s[r][c];
            }
#pragma unroll
            for (int off = 1; off < 16; off <<= 1)
                sum += __shfl_xor_sync(0xffffffffu, sum, off);
            l_i[r] = l_i[r] * alpha + sum;
            m_i[r] = mnew;
            u64 al2 = dup2(alpha);
            acc[r][0] = mul2(acc[r][0], al2);
            acc[r][1] = mul2(acc[r][1], al2);
        }

        __syncthreads();   // (C)
#pragma unroll
        for (int r = 0; r < 4; r++) {
            float4 pv;
            pv.x = s[r][0]; pv.y = s[r][1]; pv.z = s[r][2]; pv.w = s[r][3];
            *(float4*)&KP[(ty*4 + r)*64 + tx*4] = pv;
        }
        __syncthreads();   // (D)

        // O += P V, packed pairs over d-columns
#pragma unroll 16
        for (int j = 0; j < 64; j++) {
            float4 bb = *(const float4*)&Vs[j*64 + tx*4];
            u64 bp0 = pack2(bb.x, bb.y);
            u64 bp1 = pack2(bb.z, bb.w);
#pragma unroll
            for (int r = 0; r < 4; r++) {
                u64 ap = dup2(KP[(ty*4 + r)*64 + j]);
                ffma2(acc[r][0], ap, bp0);
                ffma2(acc[r][1], ap, bp1);
            }
        }
    }

    // Epilogue
    float* out = ctx + (size_t)(b * SEQ + qBase) * D_MODEL + h * 64;
#pragma unroll
    for (int r = 0; r < 4; r++) {
        float inv = 1.f / l_i[r];
        float4 o;
        unpack2(o.x, o.y, acc[r][0]);
        unpack2(o.z, o.w, acc[r][1]);
        o.x *= inv; o.y *= inv; o.z *= inv; o.w *= inv;
        *(float4*)(out + (size_t)(ty*4 + r) * D_MODEL + tx*4) = o;
    }
}

// ---------------------------------------------------------------------------
extern "C" void kernel_launch(void* const* d_in, const int* in_sizes, int n_in,
                              void* d_out, int out_size)
{
    const float* x      = (const float*)d_in[0];
    const float* qkv_w  = (const float*)d_in[1];
    const float* qkv_b  = (const float*)d_in[2];
    const float* proj_w = (const float*)d_in[3];
    const float* proj_b = (const float*)d_in[4];
    float* out = (float*)d_out;

    float *qkv, *qt, *kt, *ctx;
    cudaGetSymbolAddress((void**)&qkv, g_qkv);
    cudaGetSymbolAddress((void**)&qt,  g_qt);
    cudaGetSymbolAddress((void**)&kt,  g_kt);
    cudaGetSymbolAddress((void**)&ctx, g_ctx);

    // 1) QKV projection
    sgemm_nt_bias<<<dim3(QKV_N/128, MTOT/128), 256>>>(
        x, qkv_w, qkv_b, qkv, MTOT, QKV_N, D_MODEL);

    // 2) RoPE + transpose q,k into d-major buffers
    rope_transpose<<<dim3(SEQ/64, N_HEADS, BATCH), 256>>>(qkv, qt, kt);

    // 3) Causal flash attention -> ctx
    attn_kernel<<<dim3(SEQ/64, N_HEADS, BATCH), 256>>>(qt, kt, qkv, ctx);

    // 4) Output projection
    sgemm_nt_bias<<<dim3(D_MODEL/128, MTOT/128), 256>>>(
        ctx, proj_w, proj_b, out, MTOT, D_MODEL, D_MODEL);
}

// round 11
// speedup vs baseline: 1.5848x; 1.5848x over previous
#include <cuda_runtime.h>
#include <cuda_bf16.h>
#include <math.h>
#include <stdint.h>

#define D_MODEL 1024
#define N_HEADS 16
#define D_HEAD  64
#define SEQ     2048
#define BATCH   2
#define MTOT    (BATCH*SEQ)      /* 4096 */
#define QKV_N   (3*D_MODEL)      /* 3072 */
#define KDIM    1024

// ---------------- scratch (device globals; no allocations) -----------------
__device__ float g_qkv[(size_t)MTOT*QKV_N];
__device__ float g_qt[(size_t)BATCH*N_HEADS*D_HEAD*SEQ];
__device__ float g_kt[(size_t)BATCH*N_HEADS*D_HEAD*SEQ];
__device__ float g_ctx[(size_t)MTOT*D_MODEL];
// bf16 hi|lo row-major buffers: hi at [row][k], lo at [rows+row][k]
__device__ __nv_bfloat16 g_xt[(size_t)2*MTOT*KDIM];
__device__ __nv_bfloat16 g_wqkvt[(size_t)2*QKV_N*KDIM];
__device__ __nv_bfloat16 g_wprojt[(size_t)2*D_MODEL*KDIM];
__device__ __nv_bfloat16 g_ctxt[(size_t)2*MTOT*KDIM];

// ---------------------------- helpers --------------------------------------
static __device__ __forceinline__ uint32_t s2u(const void* p){
    uint32_t a;
    asm("{ .reg .u64 t; cvta.to.shared.u64 t, %1; cvt.u32.u64 %0, t; }"
        : "=r"(a) : "l"(p));
    return a;
}
static __device__ __forceinline__ uint32_t lds32(uint32_t a){
    uint32_t v; asm volatile("ld.shared.b32 %0, [%1];" : "=r"(v) : "r"(a)); return v;
}
static __device__ __forceinline__ void cpa16(uint32_t dst, const void* src){
    asm volatile("cp.async.ca.shared.global [%0], [%1], 16;" :: "r"(dst), "l"(src) : "memory");
}
static __device__ __forceinline__ void cpa_commit(){
    asm volatile("cp.async.commit_group;" ::: "memory");
}
template<int N> static __device__ __forceinline__ void cpa_wait(){
    asm volatile("cp.async.wait_group %0;" :: "n"(N) : "memory");
}
static __device__ __forceinline__ void mma16816(float* d, const uint32_t* a, const uint32_t* b){
    asm volatile(
        "mma.sync.aligned.m16n8k16.row.col.f32.bf16.bf16.f32 "
        "{%0,%1,%2,%3}, {%4,%5,%6,%7}, {%8,%9}, {%0,%1,%2,%3};"
        : "+f"(d[0]), "+f"(d[1]), "+f"(d[2]), "+f"(d[3])
        : "r"(a[0]), "r"(a[1]), "r"(a[2]), "r"(a[3]), "r"(b[0]), "r"(b[1]));
}

// ---------------------------------------------------------------------------
// fp32 -> bf16 hi/lo split, plain row-major. Block = one row, 256 thr x 4 col.
// ---------------------------------------------------------------------------
__global__ void conv_hilo(const float* __restrict__ src,
                          __nv_bfloat16* __restrict__ dst, int rows)
{
    int row = blockIdx.x;
    int c4 = threadIdx.x * 4;
    float4 v = *(const float4*)(src + (size_t)row * KDIM + c4);
    float f[4] = {v.x, v.y, v.z, v.w};
    unsigned short hs[4], ls[4];
#pragma unroll
    for (int i = 0; i < 4; i++) {
        __nv_bfloat16 h = __float2bfloat16(f[i]);
        float r = f[i] - __bfloat162float(h);
        hs[i] = __bfloat16_as_ushort(h);
        ls[i] = __bfloat16_as_ushort(__float2bfloat16(r));
    }
    *(ushort4*)(dst + (size_t)row * KDIM + c4) = make_ushort4(hs[0],hs[1],hs[2],hs[3]);
    *(ushort4*)(dst + ((size_t)rows + row) * KDIM + c4) = make_ushort4(ls[0],ls[1],ls[2],ls[3]);
}

// ---------------------------------------------------------------------------
// HMMA GEMM: C[m][n] = sum_k A[m][k]*B[n][k] + bias[n], bf16 hi/lo (3 terms).
// 128x128 block, 8 warps (2x4), warp 64x32, BK=32, cp.async 2-stage pipeline.
// Smem per stage: Ah|Al|Bh|Bl, each 128 rows x 80B (40 bf16, pad) = 10240 B.
// ---------------------------------------------------------------------------
#define GSM_STAGE 40960
#define GSM_TOTAL (2*GSM_STAGE)

__global__ void __launch_bounds__(256) tc_gemm(
    const __nv_bfloat16* __restrict__ At, const __nv_bfloat16* __restrict__ Bt,
    const float* __restrict__ bias, float* __restrict__ C,
    int N, int rowsA, int rowsB)
{
    extern __shared__ char smem[];
    const int tid = threadIdx.x;
    const int wid = tid >> 5, lane = tid & 31;
    const int wr = wid >> 2, wc = wid & 3;          // warp 2x4
    const uint32_t g = lane >> 2, t = lane & 3;
    const int bm = blockIdx.y * 128, bn = blockIdx.x * 128;
    const uint32_t sb = s2u(smem);

    const size_t loA = (size_t)rowsA * KDIM;
    const size_t loB = (size_t)rowsB * KDIM;

    // -- copy issue for one 128x32 chunk of all 4 parts into stage st --
    auto issue = [&](int st, int k0) {
        uint32_t base = sb + st * GSM_STAGE;
#pragma unroll
        for (int i = 0; i < 2; i++) {
            int id = tid + i * 256;                  // 0..511
            int row = id >> 2, seg = id & 3;
            uint32_t doff = (uint32_t)(row * 80 + seg * 16);
            const char* sA = (const char*)(At + (size_t)(bm + row) * KDIM + k0) + seg * 16;
            const char* sAl = (const char*)(At + loA + (size_t)(bm + row) * KDIM + k0) + seg * 16;
            const char* sB = (const char*)(Bt + (size_t)(bn + row) * KDIM + k0) + seg * 16;
            const char* sBl = (const char*)(Bt + loB + (size_t)(bn + row) * KDIM + k0) + seg * 16;
            cpa16(base + doff,         sA);
            cpa16(base + 10240 + doff, sAl);
            cpa16(base + 20480 + doff, sB);
            cpa16(base + 30720 + doff, sBl);
        }
    };

    float acc[4][4][4];
#pragma unroll
    for (int mf = 0; mf < 4; mf++)
#pragma unroll
        for (int nf = 0; nf < 4; nf++)
#pragma unroll
            for (int i = 0; i < 4; i++) acc[mf][nf][i] = 0.f;

    issue(0, 0);
    cpa_commit();

    const int NC = KDIM / 32;    // 32 chunks
    for (int c = 0; c < NC; c++) {
        if (c + 1 < NC) { issue((c + 1) & 1, (c + 1) * 32); cpa_commit(); cpa_wait<1>(); }
        else            { cpa_wait<0>(); }
        __syncthreads();

        uint32_t stb = sb + (c & 1) * GSM_STAGE;
        uint32_t aH = stb + (uint32_t)((wr * 64 + g) * 80 + t * 4);
        uint32_t aL = aH + 10240;
        uint32_t bH = stb + 20480 + (uint32_t)((wc * 32 + g) * 80 + t * 4);
        uint32_t bL = bH + 10240;

#pragma unroll
        for (int ks = 0; ks < 2; ks++) {
            uint32_t ko = ks * 32;
            uint32_t ah[4][4], al[4][4], bh[4][2], bl[4][2];
#pragma unroll
            for (int mf = 0; mf < 4; mf++) {
                uint32_t p = aH + mf * 1280 + ko;
                ah[mf][0] = lds32(p);        ah[mf][1] = lds32(p + 640);
                ah[mf][2] = lds32(p + 16);   ah[mf][3] = lds32(p + 656);
                uint32_t q = aL + mf * 1280 + ko;
                al[mf][0] = lds32(q);        al[mf][1] = lds32(q + 640);
                al[mf][2] = lds32(q + 16);   al[mf][3] = lds32(q + 656);
            }
#pragma unroll
            for (int nf = 0; nf < 4; nf++) {
                uint32_t p = bH + nf * 640 + ko;
                bh[nf][0] = lds32(p); bh[nf][1] = lds32(p + 16);
                uint32_t q = bL + nf * 640 + ko;
                bl[nf][0] = lds32(q); bl[nf][1] = lds32(q + 16);
            }
#pragma unroll
            for (int mf = 0; mf < 4; mf++)
#pragma unroll
                for (int nf = 0; nf < 4; nf++) {
                    mma16816(acc[mf][nf], ah[mf], bh[nf]);   // hi*hi
                    mma16816(acc[mf][nf], ah[mf], bl[nf]);   // hi*lo
                    mma16816(acc[mf][nf], al[mf], bh[nf]);   // lo*hi
                }
        }
        __syncthreads();
    }

    // epilogue: add bias, write fp32
#pragma unroll
    for (int mf = 0; mf < 4; mf++) {
        int row0 = bm + wr * 64 + mf * 16 + (int)g;
#pragma unroll
        for (int nf = 0; nf < 4; nf++) {
            int col = bn + wc * 32 + nf * 8 + 2 * (int)t;
            float2 bb = *(const float2*)(bias + col);
            float2 v0, v1;
            v0.x = acc[mf][nf][0] + bb.x; v0.y = acc[mf][nf][1] + bb.y;
            v1.x = acc[mf][nf][2] + bb.x; v1.y = acc[mf][nf][3] + bb.y;
            *(float2*)(C + (size_t)row0 * N + col) = v0;
            *(float2*)(C + (size_t)(row0 + 8) * N + col) = v1;
        }
    }
}

// ---------------------------------------------------------------------------
// RoPE + transpose (unchanged R5)
// ---------------------------------------------------------------------------
__global__ void __launch_bounds__(256) rope_transpose(
    const float* __restrict__ qkv, float* __restrict__ qt, float* __restrict__ kt)
{
    __shared__ float Tq[64*65];
    __shared__ float Tk[64*65];

    const int st = blockIdx.x, h = blockIdx.y, b = blockIdx.z;
    const int s0 = st * 64;
    const int tid = threadIdx.x;

#pragma unroll
    for (int l = 0; l < 4; l++) {
        int f = tid + l * 256;
        int srow = f >> 4;
        int d4 = (f & 15) * 4;
        const float* p = qkv + (size_t)(b * SEQ + s0 + srow) * QKV_N + h * 64 + d4;
        float4 qv = *(const float4*)p;
        float4 kv = *(const float4*)(p + D_MODEL);
        Tq[srow*65 + d4+0] = qv.x; Tq[srow*65 + d4+1] = qv.y;
        Tq[srow*65 + d4+2] = qv.z; Tq[srow*65 + d4+3] = qv.w;
        Tk[srow*65 + d4+0] = kv.x; Tk[srow*65 + d4+1] = kv.y;
        Tk[srow*65 + d4+2] = kv.z; Tk[srow*65 + d4+3] = kv.w;
    }
    __syncthreads();

    const size_t obase = ((size_t)(b * N_HEADS + h)) * D_HEAD * SEQ;
#pragma unroll
    for (int l = 0; l < 4; l++) {
        int f = tid + l * 256;
        int d = f >> 4;
        int s4 = (f & 15) * 4;
        int i = d & 31;
        bool hi = d >= 32;
        float inv = powf(10000.0f, -(2.0f * (float)i) / 64.0f);
        float4 oq, ok;
        float* pq = (float*)&oq;
        float* pk = (float*)&ok;
#pragma unroll
        for (int u = 0; u < 4; u++) {
            int s = s4 + u;
            float ang = (float)(s0 + s) * inv;
            float sn, cs;
            sincosf(ang, &sn, &cs);
            float q1 = Tq[s*65 + d], q2 = Tq[s*65 + (d ^ 32)];
            float k1 = Tk[s*65 + d], k2 = Tk[s*65 + (d ^ 32)];
            pq[u] = hi ? (q1 * cs + q2 * sn) : (q1 * cs - q2 * sn);
            pk[u] = hi ? (k1 * cs + k2 * sn) : (k1 * cs - k2 * sn);
        }
        *(float4*)(qt + obase + (size_t)d * SEQ + s0 + s4) = oq;
        *(float4*)(kt + obase + (size_t)d * SEQ + s0 + s4) = ok;
    }
}

// ---------------------------------------------------------------------------
// Flash attention (unchanged R5 best)
// ---------------------------------------------------------------------------
__global__ void __launch_bounds__(256, 2) attn_kernel(
    const float* __restrict__ qt, const float* __restrict__ ktb,
    const float* __restrict__ qkv, float* __restrict__ ctx)
{
    __shared__ float Qs[64*64];
    __shared__ float KP[64*64];
    __shared__ float Vs[64*64];

    const int qtile = blockIdx.x, h = blockIdx.y, b = blockIdx.z;
    const int tid = threadIdx.x;
    const int tx = tid & 15, ty = tid >> 4;
    const int qBase = qtile * 64;

    const size_t hbase = ((size_t)(b * N_HEADS + h)) * D_HEAD * SEQ;
    const float* qtp = qt + hbase;
    const float* ktp = ktb + hbase;
    const float* vbase = qkv + (size_t)b * SEQ * QKV_N + 2 * D_MODEL + h * 64;

#pragma unroll
    for (int l = 0; l < 4; l++) {
        int f = tid + l * 256;
        int d = f >> 4;
        int s4 = (f & 15) * 4;
        *(float4*)&Qs[d*64 + s4] =
            *(const float4*)(qtp + (size_t)d * SEQ + qBase + s4);
    }

    float4 kreg[4], vreg[4];
#pragma unroll
    for (int l = 0; l < 4; l++) {
        int f = tid + l * 256;
        int d = f >> 4;
        int c4 = (f & 15) * 4;
        kreg[l] = *(const float4*)(ktp + (size_t)d * SEQ + 0 + c4);
        vreg[l] = *(const float4*)(vbase + (size_t)(0 + d) * QKV_N + c4);
    }

    float m_i[4], l_i[4], acc[4][4];
#pragma unroll
    for (int r = 0; r < 4; r++) {
        m_i[r] = -1e30f; l_i[r] = 0.f;
#pragma unroll
        for (int c = 0; c < 4; c++) acc[r][c] = 0.f;
    }

    for (int kt = 0; kt <= qtile; kt++) {
        __syncthreads();

#pragma unroll
        for (int l = 0; l < 4; l++) {
            int f = tid + l * 256;
            int d = f >> 4;
            int c4 = (f & 15) * 4;
            *(float4*)&KP[d*64 + c4] = kreg[l];
            *(float4*)&Vs[d*64 + c4] = vreg[l];
        }
        __syncthreads();

        if (kt < qtile) {
            const int nBase = (kt + 1) * 64;
#pragma unroll
            for (int l = 0; l < 4; l++) {
                int f = tid + l * 256;
                int d = f >> 4;
                int c4 = (f & 15) * 4;
                kreg[l] = *(const float4*)(ktp + (size_t)d * SEQ + nBase + c4);
                vreg[l] = *(const float4*)(vbase + (size_t)(nBase + d) * QKV_N + c4);
            }
        }

        float s[4][4];
#pragma unroll
        for (int r = 0; r < 4; r++)
#pragma unroll
            for (int c = 0; c < 4; c++) s[r][c] = 0.f;
#pragma unroll 16
        for (int d = 0; d < 64; d++) {
            float4 a  = *(const float4*)&Qs[d*64 + ty*4];
            float4 bb = *(const float4*)&KP[d*64 + tx*4];
            float av[4] = {a.x, a.y, a.z, a.w};
            float bv[4] = {bb.x, bb.y, bb.z, bb.w};
#pragma unroll
            for (int r = 0; r < 4; r++)
#pragma unroll
                for (int c = 0; c < 4; c++)
                    s[r][c] = fmaf(av[r], bv[c], s[r][c]);
        }
#pragma unroll
        for (int r = 0; r < 4; r++)
#pragma unroll
            for (int c = 0; c < 4; c++) s[r][c] *= 0.125f;

        if (kt == qtile) {
#pragma unroll
            for (int r = 0; r < 4; r++)
#pragma unroll
                for (int c = 0; c < 4; c++)
                    if (tx*4 + c > ty*4 + r) s[r][c] = -1e30f;
        }

#pragma unroll
        for (int r = 0; r < 4; r++) {
            float mt = fmaxf(fmaxf(s[r][0], s[r][1]), fmaxf(s[r][2], s[r][3]));
#pragma unroll
            for (int off = 1; off < 16; off <<= 1)
                mt = fmaxf(mt, __shfl_xor_sync(0xffffffffu, mt, off));
            float mnew  = fmaxf(m_i[r], mt);
            float alpha = __expf(m_i[r] - mnew);
            float sum = 0.f;
#pragma unroll
            for (int c = 0; c < 4; c++) {
                s[r][c] = __expf(s[r][c] - mnew);
                sum += s[r][c];
            }
#pragma unroll
            for (int off = 1; off < 16; off <<= 1)
                sum += __shfl_xor_sync(0xffffffffu, sum, off);
            l_i[r] = l_i[r] * alpha + sum;
            m_i[r] = mnew;
#pragma unroll
            for (int c = 0; c < 4; c++) acc[r][c] *= alpha;
        }

        __syncthreads();
#pragma unroll
        for (int r = 0; r < 4; r++) {
            float4 pv;
            pv.x = s[r][0]; pv.y = s[r][1]; pv.z = s[r][2]; pv.w = s[r][3];
            *(float4*)&KP[(ty*4 + r)*64 + tx*4] = pv;
        }
        __syncthreads();

#pragma unroll 16
        for (int j = 0; j < 64; j++) {
            float4 bb = *(const float4*)&Vs[j*64 + tx*4];
            float bv[4] = {bb.x, bb.y, bb.z, bb.w};
            float av[4];
#pragma unroll
            for (int r = 0; r < 4; r++) av[r] = KP[(ty*4 + r)*64 + j];
#pragma unroll
            for (int r = 0; r < 4; r++)
#pragma unroll
                for (int c = 0; c < 4; c++)
                    acc[r][c] = fmaf(av[r], bv[c], acc[r][c]);
        }
    }

    float* out = ctx + (size_t)(b * SEQ + qBase) * D_MODEL + h * 64;
#pragma unroll
    for (int r = 0; r < 4; r++) {
        float inv = 1.f / l_i[r];
        float4 o;
        o.x = acc[r][0] * inv; o.y = acc[r][1] * inv;
        o.z = acc[r][2] * inv; o.w = acc[r][3] * inv;
        *(float4*)(out + (size_t)(ty*4 + r) * D_MODEL + tx*4) = o;
    }
}

// ---------------------------------------------------------------------------
extern "C" void kernel_launch(void* const* d_in, const int* in_sizes, int n_in,
                              void* d_out, int out_size)
{
    const float* x      = (const float*)d_in[0];
    const float* qkv_w  = (const float*)d_in[1];
    const float* qkv_b  = (const float*)d_in[2];
    const float* proj_w = (const float*)d_in[3];
    const float* proj_b = (const float*)d_in[4];
    float* out = (float*)d_out;

    float *qkv, *qt, *kt, *ctx;
    __nv_bfloat16 *xt, *wqkvt, *wprojt, *ctxt;
    cudaGetSymbolAddress((void**)&qkv, g_qkv);
    cudaGetSymbolAddress((void**)&qt,  g_qt);
    cudaGetSymbolAddress((void**)&kt,  g_kt);
    cudaGetSymbolAddress((void**)&ctx, g_ctx);
    cudaGetSymbolAddress((void**)&xt,     g_xt);
    cudaGetSymbolAddress((void**)&wqkvt,  g_wqkvt);
    cudaGetSymbolAddress((void**)&wprojt, g_wprojt);
    cudaGetSymbolAddress((void**)&ctxt,   g_ctxt);

    cudaFuncSetAttribute(tc_gemm, cudaFuncAttributeMaxDynamicSharedMemorySize, GSM_TOTAL);

    // 0) convert operands to bf16 hi/lo
    conv_hilo<<<MTOT,   256>>>(x,      xt,     MTOT);
    conv_hilo<<<QKV_N,  256>>>(qkv_w,  wqkvt,  QKV_N);
    conv_hilo<<<D_MODEL,256>>>(proj_w, wprojt, D_MODEL);

    // 1) QKV projection (HMMA)
    tc_gemm<<<dim3(QKV_N/128, MTOT/128), 256, GSM_TOTAL>>>(
        xt, wqkvt, qkv_b, qkv, QKV_N, MTOT, QKV_N);

    // 2) RoPE + transpose
    rope_transpose<<<dim3(SEQ/64, N_HEADS, BATCH), 256>>>(qkv, qt, kt);

    // 3) Causal flash attention -> ctx
    attn_kernel<<<dim3(SEQ/64, N_HEADS, BATCH), 256>>>(qt, kt, qkv, ctx);

    // 4) convert ctx, output projection (HMMA)
    conv_hilo<<<MTOT, 256>>>(ctx, ctxt, MTOT);
    tc_gemm<<<dim3(D_MODEL/128, MTOT/128), 256, GSM_TOTAL>>>(
        ctxt, wprojt, proj_b, out, D_MODEL, MTOT, D_MODEL);
}